// round 15
// baseline (speedup 1.0000x reference)
#include <cuda_runtime.h>
#include <math.h>

#define BB   256
#define SS   196
#define RNN  1024
#define ATTH 512
#define KSPLIT 16
#define KCHUNK 64    // RNN / KSPLIT
#define SQ   49      // SS / 4

// Split-K partials for att_h = h @ w_h2att^T (bias folded in later).
__device__ float g_atth_part[KSPLIT * BB * ATTH];   // 8 MB
// Raw (pre-softmax) scores.
__device__ float g_scores[BB * SS];                 // 200 KB

// Fast accurate tanh: tanh(x) = 1 - 2/(exp(2x)+1); 2 MUFU, ~1e-7 abs err.
__device__ __forceinline__ float fast_tanhf(float x) {
  float e;
  asm("ex2.approx.f32 %0, %1;" : "=f"(e) : "f"(x * 2.885390081777927f));
  float r;
  asm("rcp.approx.f32 %0, %1;" : "=f"(r) : "f"(e + 1.0f));
  return fmaf(-2.0f, r, 1.0f);
}

// ---------------------------------------------------------------------------
// Kernel 1: split-K GEMM, 32(m) x 64(n) x 64(k), broadcast A microtile,
// XOR-swizzled smem. Whole grid (1024 blocks) is co-resident, so the early
// launch_dependents lets the scores grid start prefetching p_att into L2
// while this kernel owns compute (DRAM here is ~2.6% busy).
// Grid: (ATTH/64, BB/32, KSPLIT) = (8, 8, 16) = 1024 blocks, 256 threads.
// ---------------------------------------------------------------------------
__global__ __launch_bounds__(256) void gemm_atth_kernel(
    const float* __restrict__ h, const float* __restrict__ w) {
  // Early PDL trigger: all CTAs are resident in wave 1 (1024 < capacity),
  // so dependents may launch into spare slots right away.
  asm volatile("griddepcontrol.launch_dependents;");

  const int n0 = blockIdx.x * 64;
  const int m0 = blockIdx.y * 32;
  const int k0 = blockIdx.z * KCHUNK;
  const int t  = threadIdx.x;        // 0..255

  __shared__ float As[KCHUNK][32];   // [k][m], phys m = m ^ ((k>>3)<<2)
  __shared__ float Bs[KCHUNK][64];   // [k][n], phys n = n ^ ((k>>2&7)<<3)

  // ---- Load A tile (32m x 64k), transposed+swizzled. 8 floats/thread. ----
  {
    const int r  = t >> 3;           // m row 0..31
    const int c0 = (t & 7) * 8;      // k base; (c>>3)&7 == t&7 for all 8 c
    const int pa = r ^ ((t & 7) << 2);
    const float* src = h + (size_t)(m0 + r) * RNN + k0 + c0;
    const float4 v0 = *(const float4*)(src);
    const float4 v1 = *(const float4*)(src + 4);
    As[c0 + 0][pa] = v0.x; As[c0 + 1][pa] = v0.y;
    As[c0 + 2][pa] = v0.z; As[c0 + 3][pa] = v0.w;
    As[c0 + 4][pa] = v1.x; As[c0 + 5][pa] = v1.y;
    As[c0 + 6][pa] = v1.z; As[c0 + 7][pa] = v1.w;
  }
  // ---- Load B tile (64n x 64k), transposed+swizzled. 16 floats/thread. ----
  {
    const int r  = t >> 2;           // n row 0..63
    const int c0 = (t & 3) * 4;      // k base
    const float* src = w + (size_t)(n0 + r) * RNN + k0;
#pragma unroll
    for (int i = 0; i < 4; i++) {
      const int c  = c0 + i * 16;
      const int pb = r ^ ((((t & 3) + 4 * i) & 7) << 3);
      const float4 v = *(const float4*)(src + c);
      Bs[c + 0][pb] = v.x; Bs[c + 1][pb] = v.y;
      Bs[c + 2][pb] = v.z; Bs[c + 3][pb] = v.w;
    }
  }
  __syncthreads();

  const int warp = t >> 5;
  const int lane = t & 31;
  const int w4   = warp * 4;
  const int l2   = lane * 2;

  unsigned long long acc[2][2] = {{0ull, 0ull}, {0ull, 0ull}};

#pragma unroll 16
  for (int k = 0; k < KCHUNK; k++) {
    const int swa = ((k >> 3) & 7) << 2;
    const int swb = ((k >> 2) & 7) << 3;
    // A: one broadcast LDS.128 directly into packed u64 pair (no movs).
    const ulonglong2 av = *(const ulonglong2*)&As[k][w4 ^ swa];
    const float2 b = *(const float2*)&Bs[k][l2 ^ swb];  // conflict-free LDS.64
    unsigned long long b0, b1;
    asm("mov.b64 %0, {%1, %1};" : "=l"(b0) : "r"(__float_as_uint(b.x)));
    asm("mov.b64 %0, {%1, %1};" : "=l"(b1) : "r"(__float_as_uint(b.y)));
    asm("fma.rn.f32x2 %0, %1, %2, %0;" : "+l"(acc[0][0]) : "l"(av.x), "l"(b0));
    asm("fma.rn.f32x2 %0, %1, %2, %0;" : "+l"(acc[0][1]) : "l"(av.y), "l"(b0));
    asm("fma.rn.f32x2 %0, %1, %2, %0;" : "+l"(acc[1][0]) : "l"(av.x), "l"(b1));
    asm("fma.rn.f32x2 %0, %1, %2, %0;" : "+l"(acc[1][1]) : "l"(av.y), "l"(b1));
  }

  float* dst = g_atth_part + (size_t)blockIdx.z * BB * ATTH;
#pragma unroll
  for (int i = 0; i < 4; i++) {
    const int p = i >> 1, hi = i & 1;
    float2 o;
    o.x = __uint_as_float(hi ? (unsigned)(acc[0][p] >> 32) : (unsigned)acc[0][p]);
    o.y = __uint_as_float(hi ? (unsigned)(acc[1][p] >> 32) : (unsigned)acc[1][p]);
    *(float2*)(dst + (size_t)(m0 + w4 + i) * ATTH + n0 + l2) = o;
  }
}

// ---------------------------------------------------------------------------
// Kernel 2: raw scores (PDL secondary of gemm; launches early).
// Before the grid-dependency wait: stage bias/w_alpha in smem AND issue
// L2 prefetches for this block's 100 KB p_att slice — DRAM is idle while
// the gemm computes, so p_att lands in L2 ahead of the streaming reads.
// Grid: (BB, 4) = 1024 blocks, 256 threads. Block (b,q) handles 49 s-rows.
// ---------------------------------------------------------------------------
__global__ __launch_bounds__(256) void scores_kernel(
    const float* __restrict__ p_att,
    const float* __restrict__ b_h2att,
    const float* __restrict__ w_alpha) {
  __shared__ __align__(16) float sh_atth[ATTH];
  __shared__ __align__(16) float sh_wa[ATTH];

  const int b    = blockIdx.x;
  const int q    = blockIdx.y;
  const int tid  = threadIdx.x;
  const int warp = tid >> 5;
  const int lane = tid & 31;

  const float* pbase = p_att + (size_t)b * SS * ATTH + (size_t)q * SQ * ATTH;

  // Independent prologue (runs while gemm occupies the SMs).
#pragma unroll
  for (int a = tid; a < ATTH; a += 256) {
    sh_atth[a] = b_h2att[a];
    sh_wa[a]   = w_alpha[a];
  }
  // Prefetch this block's p_att slice into L2: 49*512*4B = 784 x 128B lines.
  for (int i = tid; i < (SQ * ATTH) / 32; i += 256)
    asm volatile("prefetch.global.L2 [%0];" :: "l"(pbase + (size_t)i * 32));

  asm volatile("griddepcontrol.wait;");   // gemm results now visible

#pragma unroll
  for (int a = tid; a < ATTH; a += 256) {
    float v = sh_atth[a];
#pragma unroll
    for (int z = 0; z < KSPLIT; z++)
      v += g_atth_part[(size_t)z * BB * ATTH + (size_t)b * ATTH + a];
    sh_atth[a] = v;
  }
  __syncthreads();

  for (int sl = warp; sl < SQ; sl += 8) {
    const float* row = pbase + (size_t)sl * ATTH;
    float acc = 0.f;
#pragma unroll
    for (int i = 0; i < 4; i++) {
      const int a = i * 128 + lane * 4;
      const float4 p  = *(const float4*)(row + a);
      const float4 ah = *(const float4*)(sh_atth + a);
      const float4 wa = *(const float4*)(sh_wa + a);
      acc = fmaf(fast_tanhf(p.x + ah.x), wa.x, acc);
      acc = fmaf(fast_tanhf(p.y + ah.y), wa.y, acc);
      acc = fmaf(fast_tanhf(p.z + ah.z), wa.z, acc);
      acc = fmaf(fast_tanhf(p.w + ah.w), wa.w, acc);
    }
#pragma unroll
    for (int off = 16; off > 0; off >>= 1)
      acc += __shfl_xor_sync(0xffffffffu, acc, off);
    if (lane == 0) g_scores[(size_t)b * SS + q * SQ + sl] = acc;
  }
}

// ---------------------------------------------------------------------------
// Kernel 3: softmax prologue + weighted sum (PDL secondary of scores).
//   out[b, q*256+t] = sum_s softmax(scores[b])[s] * att_feats[b,s,q*256+t]
// Grid: (BB, 4) = 1024 blocks, 256 threads, 1 output dim per thread.
// ---------------------------------------------------------------------------
__global__ __launch_bounds__(256) void wsum_kernel(
    const float* __restrict__ att_feats,
    float* __restrict__ out) {
  __shared__ float sh_w[SS];
  __shared__ float red[8];

  const int b    = blockIdx.x;
  const int q    = blockIdx.y;
  const int tid  = threadIdx.x;
  const int warp = tid >> 5;
  const int lane = tid & 31;

  asm volatile("griddepcontrol.wait;");   // scores now visible

  // --- softmax over 196 scores ---
  const float v = (tid < SS) ? g_scores[(size_t)b * SS + tid] : -INFINITY;

  float m = v;
#pragma unroll
  for (int off = 16; off > 0; off >>= 1)
    m = fmaxf(m, __shfl_xor_sync(0xffffffffu, m, off));
  if (lane == 0) red[warp] = m;
  __syncthreads();
  m = red[0];
#pragma unroll
  for (int i = 1; i < 8; i++) m = fmaxf(m, red[i]);
  __syncthreads();

  const float e = (tid < SS) ? __expf(v - m) : 0.f;
  float sum = e;
#pragma unroll
  for (int off = 16; off > 0; off >>= 1)
    sum += __shfl_xor_sync(0xffffffffu, sum, off);
  if (lane == 0) red[warp] = sum;
  __syncthreads();
  float tot = red[0];
#pragma unroll
  for (int i = 1; i < 8; i++) tot += red[i];
  const float inv = 1.f / tot;
  if (tid < SS) sh_w[tid] = e * inv;
  __syncthreads();

  // --- stream att_feats: 196 coalesced scalar loads per thread ---
  const int d = q * 256 + tid;
  const float* ab = att_feats + (size_t)b * SS * RNN + d;
  float acc = 0.f;
#pragma unroll 4
  for (int s = 0; s < SS; s++)
    acc = fmaf(sh_w[s], ab[(size_t)s * RNN], acc);

  out[(size_t)b * RNN + d] = acc;
}

// ---------------------------------------------------------------------------
// Launch. Inputs: h, att_feats, p_att_feats, w_h2att, b_h2att, w_alpha,
// b_alpha (unused: softmax shift-invariant). scores/wsum are PDL
// secondaries; gemm triggers early so scores can prefetch during gemm.
// ---------------------------------------------------------------------------
extern "C" void kernel_launch(void* const* d_in, const int* in_sizes, int n_in,
                              void* d_out, int out_size) {
  (void)in_sizes; (void)n_in; (void)out_size;
  const float* h         = (const float*)d_in[0];
  const float* att_feats = (const float*)d_in[1];
  const float* p_att     = (const float*)d_in[2];
  const float* w_h2att   = (const float*)d_in[3];
  const float* b_h2att   = (const float*)d_in[4];
  const float* w_alpha   = (const float*)d_in[5];
  float* out = (float*)d_out;

  dim3 g1(ATTH / 64, BB / 32, KSPLIT);      // (8, 8, 16) = 1024 blocks
  gemm_atth_kernel<<<g1, 256>>>(h, w_h2att);

  cudaLaunchAttribute attr[1];
  attr[0].id = cudaLaunchAttributeProgrammaticStreamSerialization;
  attr[0].val.programmaticStreamSerializationAllowed = 1;

  {
    cudaLaunchConfig_t cfg = {};
    cfg.gridDim  = dim3(BB, 4);
    cfg.blockDim = dim3(256);
    cfg.stream   = 0;
    cfg.attrs    = attr;
    cfg.numAttrs = 1;
    cudaLaunchKernelEx(&cfg, scores_kernel, p_att, b_h2att, w_alpha);
  }
  {
    cudaLaunchConfig_t cfg = {};
    cfg.gridDim  = dim3(BB, 4);
    cfg.blockDim = dim3(256);
    cfg.stream   = 0;
    cfg.attrs    = attr;
    cfg.numAttrs = 1;
    cudaLaunchKernelEx(&cfg, wsum_kernel, att_feats, out);
  }
}

// round 16
// speedup vs baseline: 1.0359x; 1.0359x over previous
#include <cuda_runtime.h>
#include <math.h>

#define BB   256
#define SS   196
#define RNN  1024
#define ATTH 512
#define KSPLIT 32
#define KCHUNK 32    // RNN / KSPLIT
#define SQ   49      // SS / 4

// Split-K partials for att_h = h @ w_h2att^T (bias folded in later).
__device__ float g_atth_part[KSPLIT * BB * ATTH];   // 16 MB
// Raw (pre-softmax) scores.
__device__ float g_scores[BB * SS];                 // 200 KB

// Fast accurate tanh: tanh(x) = 1 - 2/(exp(2x)+1); 2 MUFU, ~1e-7 abs err.
__device__ __forceinline__ float fast_tanhf(float x) {
  float e;
  asm("ex2.approx.f32 %0, %1;" : "=f"(e) : "f"(x * 2.885390081777927f));
  float r;
  asm("rcp.approx.f32 %0, %1;" : "=f"(r) : "f"(e + 1.0f));
  return fmaf(-2.0f, r, 1.0f);
}

// ---------------------------------------------------------------------------
// Kernel 1: split-K GEMM, 64(m) x 64(n) x 32(k), 8 m-rows per warp.
//   A main-loop read: 2 warp-uniform broadcast LDS.128 (8 m floats).
//   B main-loop read: conflict-free float2 per lane.
//   -> 4 LDS wavefronts per 8 FMA64 (0.5 wf/FMA64, was 0.75).
// XOR swizzle phys = logical ^ ((k>>3)<<3) makes all STS conflict-free and
// keeps reads aligned (sw only touches bits 3-4; rows stay contiguous).
// Grid: (ATTH/64, BB/64, KSPLIT) = (8, 4, 32) = 1024 blocks, 256 threads.
// ---------------------------------------------------------------------------
__global__ __launch_bounds__(256) void gemm_atth_kernel(
    const float* __restrict__ h, const float* __restrict__ w) {
  const int n0 = blockIdx.x * 64;
  const int m0 = blockIdx.y * 64;
  const int k0 = blockIdx.z * KCHUNK;
  const int t  = threadIdx.x;        // 0..255

  __shared__ float As[KCHUNK][64];   // [k][m], phys m = m ^ ((k>>3)<<3)
  __shared__ float Bs[KCHUNK][64];   // [k][n], phys n = n ^ ((k>>3)<<3)

  // ---- Load A tile (64m x 32k), transposed+swizzled. 8 floats/thread. ----
  // r = t>>2 (0..63), c0 = (t&3)*8; (c>>3) == t&3 for all 8 c values, so the
  // phys column r ^ ((t&3)<<3) is constant per thread and STS banks
  // (r + (t&3)*8) are all-distinct within each warp.
  {
    const int r  = t >> 2;
    const int c0 = (t & 3) * 8;
    const int pa = r ^ ((t & 3) << 3);
    const float* src = h + (size_t)(m0 + r) * RNN + k0 + c0;
    const float4 v0 = *(const float4*)(src);
    const float4 v1 = *(const float4*)(src + 4);
    As[c0 + 0][pa] = v0.x; As[c0 + 1][pa] = v0.y;
    As[c0 + 2][pa] = v0.z; As[c0 + 3][pa] = v0.w;
    As[c0 + 4][pa] = v1.x; As[c0 + 5][pa] = v1.y;
    As[c0 + 6][pa] = v1.z; As[c0 + 7][pa] = v1.w;
  }
  // ---- Load B tile (64n x 32k), same pattern. 8 floats/thread. ----
  {
    const int r  = t >> 2;
    const int c0 = (t & 3) * 8;
    const int pb = r ^ ((t & 3) << 3);
    const float* src = w + (size_t)(n0 + r) * RNN + k0 + c0;
    const float4 v0 = *(const float4*)(src);
    const float4 v1 = *(const float4*)(src + 4);
    Bs[c0 + 0][pb] = v0.x; Bs[c0 + 1][pb] = v0.y;
    Bs[c0 + 2][pb] = v0.z; Bs[c0 + 3][pb] = v0.w;
    Bs[c0 + 4][pb] = v1.x; Bs[c0 + 5][pb] = v1.y;
    Bs[c0 + 6][pb] = v1.z; Bs[c0 + 7][pb] = v1.w;
  }
  __syncthreads();

  const int warp = t >> 5;           // m rows 8*warp .. 8*warp+7
  const int lane = t & 31;           // n cols 2*lane, 2*lane+1
  const int w8   = warp * 8;
  const int l2   = lane * 2;

  // acc[p][j]: packed m-rows (w8+2p, w8+2p+1), col (n0+l2+j).
  unsigned long long acc[4][2] = {{0ull,0ull},{0ull,0ull},{0ull,0ull},{0ull,0ull}};

#pragma unroll
  for (int k = 0; k < KCHUNK; k++) {
    const int sw = ((k >> 3) & 3) << 3;                 // compile-time
    // Logical cols w8..w8+7 map to contiguous phys (w8^sw)..(w8^sw)+7:
    // sw lives in bits 3-4, j in bits 0-2.
    const ulonglong2 a0 = *(const ulonglong2*)&As[k][(w8 ^ sw)];      // m 0-3
    const ulonglong2 a1 = *(const ulonglong2*)&As[k][(w8 ^ sw) + 4];  // m 4-7
    const float2 b = *(const float2*)&Bs[k][l2 ^ sw];   // conflict-free
    unsigned long long b0, b1;
    asm("mov.b64 %0, {%1, %1};" : "=l"(b0) : "r"(__float_as_uint(b.x)));
    asm("mov.b64 %0, {%1, %1};" : "=l"(b1) : "r"(__float_as_uint(b.y)));
    asm("fma.rn.f32x2 %0, %1, %2, %0;" : "+l"(acc[0][0]) : "l"(a0.x), "l"(b0));
    asm("fma.rn.f32x2 %0, %1, %2, %0;" : "+l"(acc[1][0]) : "l"(a0.y), "l"(b0));
    asm("fma.rn.f32x2 %0, %1, %2, %0;" : "+l"(acc[2][0]) : "l"(a1.x), "l"(b0));
    asm("fma.rn.f32x2 %0, %1, %2, %0;" : "+l"(acc[3][0]) : "l"(a1.y), "l"(b0));
    asm("fma.rn.f32x2 %0, %1, %2, %0;" : "+l"(acc[0][1]) : "l"(a0.x), "l"(b1));
    asm("fma.rn.f32x2 %0, %1, %2, %0;" : "+l"(acc[1][1]) : "l"(a0.y), "l"(b1));
    asm("fma.rn.f32x2 %0, %1, %2, %0;" : "+l"(acc[2][1]) : "l"(a1.x), "l"(b1));
    asm("fma.rn.f32x2 %0, %1, %2, %0;" : "+l"(acc[3][1]) : "l"(a1.y), "l"(b1));
  }

  // Store 8 rows x 2 cols; lanes cover 64 consecutive n -> coalesced float2.
  float* dst = g_atth_part + (size_t)blockIdx.z * BB * ATTH;
#pragma unroll
  for (int p = 0; p < 4; p++) {
#pragma unroll
    for (int hi = 0; hi < 2; hi++) {
      float2 o;
      o.x = __uint_as_float(hi ? (unsigned)(acc[p][0] >> 32) : (unsigned)acc[p][0]);
      o.y = __uint_as_float(hi ? (unsigned)(acc[p][1] >> 32) : (unsigned)acc[p][1]);
      *(float2*)(dst + (size_t)(m0 + w8 + p * 2 + hi) * ATTH + n0 + l2) = o;
    }
  }
}

// ---------------------------------------------------------------------------
// Kernel 2: raw scores (PDL secondary of gemm).
//   scores[b,s] = sum_a tanh(p_att[b,s,a] + att_h[b,a] + bias[a]) * w_alpha[a]
// Grid: (BB, 4) = 1024 blocks, 256 threads. Block (b,q) handles 49 s-rows.
// w_alpha/bias staging is GEMM-independent and runs before the grid-dep sync.
// ---------------------------------------------------------------------------
__global__ __launch_bounds__(256) void scores_kernel(
    const float* __restrict__ p_att,
    const float* __restrict__ b_h2att,
    const float* __restrict__ w_alpha) {
  __shared__ __align__(16) float sh_atth[ATTH];
  __shared__ __align__(16) float sh_wa[ATTH];

  const int b    = blockIdx.x;
  const int q    = blockIdx.y;
  const int tid  = threadIdx.x;
  const int warp = tid >> 5;
  const int lane = tid & 31;

  // Independent prologue (overlaps with gemm tail under PDL).
#pragma unroll
  for (int a = tid; a < ATTH; a += 256) {
    sh_atth[a] = b_h2att[a];
    sh_wa[a]   = w_alpha[a];
  }

#if defined(__CUDA_ARCH__)
  cudaGridDependencySynchronize();   // gemm results now visible
#endif

#pragma unroll
  for (int a = tid; a < ATTH; a += 256) {
    float v = sh_atth[a];
#pragma unroll
    for (int z = 0; z < KSPLIT; z++)
      v += g_atth_part[(size_t)z * BB * ATTH + (size_t)b * ATTH + a];
    sh_atth[a] = v;
  }
  __syncthreads();

  const float* pbase = p_att + (size_t)b * SS * ATTH + (size_t)q * SQ * ATTH;
  for (int sl = warp; sl < SQ; sl += 8) {
    const float* row = pbase + (size_t)sl * ATTH;
    float acc = 0.f;
#pragma unroll
    for (int i = 0; i < 4; i++) {
      const int a = i * 128 + lane * 4;
      const float4 p  = *(const float4*)(row + a);
      const float4 ah = *(const float4*)(sh_atth + a);
      const float4 wa = *(const float4*)(sh_wa + a);
      acc = fmaf(fast_tanhf(p.x + ah.x), wa.x, acc);
      acc = fmaf(fast_tanhf(p.y + ah.y), wa.y, acc);
      acc = fmaf(fast_tanhf(p.z + ah.z), wa.z, acc);
      acc = fmaf(fast_tanhf(p.w + ah.w), wa.w, acc);
    }
#pragma unroll
    for (int off = 16; off > 0; off >>= 1)
      acc += __shfl_xor_sync(0xffffffffu, acc, off);
    if (lane == 0) g_scores[(size_t)b * SS + q * SQ + sl] = acc;
  }
}

// ---------------------------------------------------------------------------
// Kernel 3: softmax prologue + weighted sum (PDL secondary of scores).
//   out[b, q*256+t] = sum_s softmax(scores[b])[s] * att_feats[b,s,q*256+t]
// Grid: (BB, 4) = 1024 blocks, 256 threads, 1 output dim per thread.
// ---------------------------------------------------------------------------
__global__ __launch_bounds__(256) void wsum_kernel(
    const float* __restrict__ att_feats,
    float* __restrict__ out) {
  __shared__ float sh_w[SS];
  __shared__ float red[8];

  const int b    = blockIdx.x;
  const int q    = blockIdx.y;
  const int tid  = threadIdx.x;
  const int warp = tid >> 5;
  const int lane = tid & 31;

#if defined(__CUDA_ARCH__)
  cudaGridDependencySynchronize();   // scores now visible
#endif

  // --- softmax over 196 scores ---
  const float v = (tid < SS) ? g_scores[(size_t)b * SS + tid] : -INFINITY;

  float m = v;
#pragma unroll
  for (int off = 16; off > 0; off >>= 1)
    m = fmaxf(m, __shfl_xor_sync(0xffffffffu, m, off));
  if (lane == 0) red[warp] = m;
  __syncthreads();
  m = red[0];
#pragma unroll
  for (int i = 1; i < 8; i++) m = fmaxf(m, red[i]);
  __syncthreads();

  const float e = (tid < SS) ? __expf(v - m) : 0.f;
  float sum = e;
#pragma unroll
  for (int off = 16; off > 0; off >>= 1)
    sum += __shfl_xor_sync(0xffffffffu, sum, off);
  if (lane == 0) red[warp] = sum;
  __syncthreads();
  float tot = red[0];
#pragma unroll
  for (int i = 1; i < 8; i++) tot += red[i];
  const float inv = 1.f / tot;
  if (tid < SS) sh_w[tid] = e * inv;
  __syncthreads();

  // --- stream att_feats: 196 coalesced scalar loads per thread ---
  const int d = q * 256 + tid;
  const float* ab = att_feats + (size_t)b * SS * RNN + d;
  float acc = 0.f;
#pragma unroll 4
  for (int s = 0; s < SS; s++)
    acc = fmaf(sh_w[s], ab[(size_t)s * RNN], acc);

  out[(size_t)b * RNN + d] = acc;
}

// ---------------------------------------------------------------------------
// Launch. Inputs: h, att_feats, p_att_feats, w_h2att, b_h2att, w_alpha,
// b_alpha (unused: softmax shift-invariant). scores/wsum are PDL secondaries
// (plain kernel-exit trigger — early trigger + prefetch regressed in R15).
// ---------------------------------------------------------------------------
extern "C" void kernel_launch(void* const* d_in, const int* in_sizes, int n_in,
                              void* d_out, int out_size) {
  (void)in_sizes; (void)n_in; (void)out_size;
  const float* h         = (const float*)d_in[0];
  const float* att_feats = (const float*)d_in[1];
  const float* p_att     = (const float*)d_in[2];
  const float* w_h2att   = (const float*)d_in[3];
  const float* b_h2att   = (const float*)d_in[4];
  const float* w_alpha   = (const float*)d_in[5];
  float* out = (float*)d_out;

  dim3 g1(ATTH / 64, BB / 64, KSPLIT);      // (8, 4, 32) = 1024 blocks
  gemm_atth_kernel<<<g1, 256>>>(h, w_h2att);

  cudaLaunchAttribute attr[1];
  attr[0].id = cudaLaunchAttributeProgrammaticStreamSerialization;
  attr[0].val.programmaticStreamSerializationAllowed = 1;

  {
    cudaLaunchConfig_t cfg = {};
    cfg.gridDim  = dim3(BB, 4);
    cfg.blockDim = dim3(256);
    cfg.stream   = 0;
    cfg.attrs    = attr;
    cfg.numAttrs = 1;
    cudaLaunchKernelEx(&cfg, scores_kernel, p_att, b_h2att, w_alpha);
  }
  {
    cudaLaunchConfig_t cfg = {};
    cfg.gridDim  = dim3(BB, 4);
    cfg.blockDim = dim3(256);
    cfg.stream   = 0;
    cfg.attrs    = attr;
    cfg.numAttrs = 1;
    cudaLaunchKernelEx(&cfg, wsum_kernel, att_feats, out);
  }
}

// round 17
// speedup vs baseline: 1.0537x; 1.0172x over previous
#include <cuda_runtime.h>
#include <math.h>

#define BB   256
#define SS   196
#define RNN  1024
#define ATTH 512
#define KSPLIT 32
#define KCHUNK 32    // RNN / KSPLIT
#define SQ   49      // SS / 4

// Split-K partials for att_h = h @ w_h2att^T.
__device__ float g_atth_part[KSPLIT * BB * ATTH];   // 16 MB
// Reduced att_h (bias folded in).
__device__ float g_atth[BB * ATTH];                 // 512 KB
// Raw (pre-softmax) scores.
__device__ float g_scores[BB * SS];                 // 200 KB

// Fast accurate tanh: tanh(x) = 1 - 2/(exp(2x)+1); 2 MUFU, ~1e-7 abs err.
__device__ __forceinline__ float fast_tanhf(float x) {
  float e;
  asm("ex2.approx.f32 %0, %1;" : "=f"(e) : "f"(x * 2.885390081777927f));
  float r;
  asm("rcp.approx.f32 %0, %1;" : "=f"(r) : "f"(e + 1.0f));
  return fmaf(-2.0f, r, 1.0f);
}

// ---------------------------------------------------------------------------
// Kernel 1: split-K GEMM, 64(m) x 64(n) x 32(k), 8 m-rows per warp.
// 0.5 LDS wavefronts per FMA64 (A reads are warp-uniform broadcasts).
// Grid: (ATTH/64, BB/64, KSPLIT) = (8, 4, 32) = 1024 blocks, 256 threads.
// ---------------------------------------------------------------------------
__global__ __launch_bounds__(256) void gemm_atth_kernel(
    const float* __restrict__ h, const float* __restrict__ w) {
  const int n0 = blockIdx.x * 64;
  const int m0 = blockIdx.y * 64;
  const int k0 = blockIdx.z * KCHUNK;
  const int t  = threadIdx.x;        // 0..255

  __shared__ float As[KCHUNK][64];   // [k][m], phys m = m ^ ((k>>3)<<3)
  __shared__ float Bs[KCHUNK][64];   // [k][n], phys n = n ^ ((k>>3)<<3)

  // ---- Load A tile (64m x 32k), transposed+swizzled. 8 floats/thread. ----
  {
    const int r  = t >> 2;
    const int c0 = (t & 3) * 8;
    const int pa = r ^ ((t & 3) << 3);
    const float* src = h + (size_t)(m0 + r) * RNN + k0 + c0;
    const float4 v0 = *(const float4*)(src);
    const float4 v1 = *(const float4*)(src + 4);
    As[c0 + 0][pa] = v0.x; As[c0 + 1][pa] = v0.y;
    As[c0 + 2][pa] = v0.z; As[c0 + 3][pa] = v0.w;
    As[c0 + 4][pa] = v1.x; As[c0 + 5][pa] = v1.y;
    As[c0 + 6][pa] = v1.z; As[c0 + 7][pa] = v1.w;
  }
  // ---- Load B tile (64n x 32k), same pattern. 8 floats/thread. ----
  {
    const int r  = t >> 2;
    const int c0 = (t & 3) * 8;
    const int pb = r ^ ((t & 3) << 3);
    const float* src = w + (size_t)(n0 + r) * RNN + k0 + c0;
    const float4 v0 = *(const float4*)(src);
    const float4 v1 = *(const float4*)(src + 4);
    Bs[c0 + 0][pb] = v0.x; Bs[c0 + 1][pb] = v0.y;
    Bs[c0 + 2][pb] = v0.z; Bs[c0 + 3][pb] = v0.w;
    Bs[c0 + 4][pb] = v1.x; Bs[c0 + 5][pb] = v1.y;
    Bs[c0 + 6][pb] = v1.z; Bs[c0 + 7][pb] = v1.w;
  }
  __syncthreads();

  const int warp = t >> 5;           // m rows 8*warp .. 8*warp+7
  const int lane = t & 31;           // n cols 2*lane, 2*lane+1
  const int w8   = warp * 8;
  const int l2   = lane * 2;

  unsigned long long acc[4][2] = {{0ull,0ull},{0ull,0ull},{0ull,0ull},{0ull,0ull}};

#pragma unroll
  for (int k = 0; k < KCHUNK; k++) {
    const int sw = ((k >> 3) & 3) << 3;                 // compile-time
    const ulonglong2 a0 = *(const ulonglong2*)&As[k][(w8 ^ sw)];      // m 0-3
    const ulonglong2 a1 = *(const ulonglong2*)&As[k][(w8 ^ sw) + 4];  // m 4-7
    const float2 b = *(const float2*)&Bs[k][l2 ^ sw];   // conflict-free
    unsigned long long b0, b1;
    asm("mov.b64 %0, {%1, %1};" : "=l"(b0) : "r"(__float_as_uint(b.x)));
    asm("mov.b64 %0, {%1, %1};" : "=l"(b1) : "r"(__float_as_uint(b.y)));
    asm("fma.rn.f32x2 %0, %1, %2, %0;" : "+l"(acc[0][0]) : "l"(a0.x), "l"(b0));
    asm("fma.rn.f32x2 %0, %1, %2, %0;" : "+l"(acc[1][0]) : "l"(a0.y), "l"(b0));
    asm("fma.rn.f32x2 %0, %1, %2, %0;" : "+l"(acc[2][0]) : "l"(a1.x), "l"(b0));
    asm("fma.rn.f32x2 %0, %1, %2, %0;" : "+l"(acc[3][0]) : "l"(a1.y), "l"(b0));
    asm("fma.rn.f32x2 %0, %1, %2, %0;" : "+l"(acc[0][1]) : "l"(a0.x), "l"(b1));
    asm("fma.rn.f32x2 %0, %1, %2, %0;" : "+l"(acc[1][1]) : "l"(a0.y), "l"(b1));
    asm("fma.rn.f32x2 %0, %1, %2, %0;" : "+l"(acc[2][1]) : "l"(a1.x), "l"(b1));
    asm("fma.rn.f32x2 %0, %1, %2, %0;" : "+l"(acc[3][1]) : "l"(a1.y), "l"(b1));
  }

  float* dst = g_atth_part + (size_t)blockIdx.z * BB * ATTH;
#pragma unroll
  for (int p = 0; p < 4; p++) {
#pragma unroll
    for (int hi = 0; hi < 2; hi++) {
      float2 o;
      o.x = __uint_as_float(hi ? (unsigned)(acc[p][0] >> 32) : (unsigned)acc[p][0]);
      o.y = __uint_as_float(hi ? (unsigned)(acc[p][1] >> 32) : (unsigned)acc[p][1]);
      *(float2*)(dst + (size_t)(m0 + w8 + p * 2 + hi) * ATTH + n0 + l2) = o;
    }
  }
}

// ---------------------------------------------------------------------------
// Kernel 1b: reduce split-K partials ONCE (PDL secondary of gemm).
//   g_atth[b][a] = bias[a] + sum_z part[z][b][a]
// Reads 16 MB (L2-hot from gemm), writes 512 KB. Fixed-order: deterministic.
// Grid: 512 blocks, 256 threads, 1 element per thread.
// ---------------------------------------------------------------------------
__global__ __launch_bounds__(256) void reduce_atth_kernel(
    const float* __restrict__ b_h2att) {
  const int i = blockIdx.x * 256 + threadIdx.x;   // 0..BB*ATTH-1
  const float bias = b_h2att[i & (ATTH - 1)];     // independent of gemm

#if defined(__CUDA_ARCH__)
  cudaGridDependencySynchronize();
#endif

  float v = bias;
#pragma unroll
  for (int z = 0; z < KSPLIT; z++)
    v += g_atth_part[(size_t)z * BB * ATTH + i];
  g_atth[i] = v;
}

// ---------------------------------------------------------------------------
// Kernel 2: raw scores (PDL secondary of reduce).
//   scores[b,s] = sum_a tanh(p_att[b,s,a] + att_h[b,a]) * w_alpha[a]
// Grid: (BB, 4) = 1024 blocks, 256 threads. Block (b,q) handles 49 s-rows.
// ---------------------------------------------------------------------------
__global__ __launch_bounds__(256) void scores_kernel(
    const float* __restrict__ p_att,
    const float* __restrict__ w_alpha) {
  __shared__ __align__(16) float sh_atth[ATTH];
  __shared__ __align__(16) float sh_wa[ATTH];

  const int b    = blockIdx.x;
  const int q    = blockIdx.y;
  const int tid  = threadIdx.x;
  const int warp = tid >> 5;
  const int lane = tid & 31;

  // Independent prologue (overlaps with predecessor tail under PDL).
#pragma unroll
  for (int a = tid; a < ATTH; a += 256) sh_wa[a] = w_alpha[a];

#if defined(__CUDA_ARCH__)
  cudaGridDependencySynchronize();   // reduced att_h now visible
#endif

#pragma unroll
  for (int a = tid; a < ATTH; a += 256)
    sh_atth[a] = g_atth[(size_t)b * ATTH + a];
  __syncthreads();

  const float* pbase = p_att + (size_t)b * SS * ATTH + (size_t)q * SQ * ATTH;
  for (int sl = warp; sl < SQ; sl += 8) {
    const float* row = pbase + (size_t)sl * ATTH;
    float acc = 0.f;
#pragma unroll
    for (int i = 0; i < 4; i++) {
      const int a = i * 128 + lane * 4;
      const float4 p  = *(const float4*)(row + a);
      const float4 ah = *(const float4*)(sh_atth + a);
      const float4 wa = *(const float4*)(sh_wa + a);
      acc = fmaf(fast_tanhf(p.x + ah.x), wa.x, acc);
      acc = fmaf(fast_tanhf(p.y + ah.y), wa.y, acc);
      acc = fmaf(fast_tanhf(p.z + ah.z), wa.z, acc);
      acc = fmaf(fast_tanhf(p.w + ah.w), wa.w, acc);
    }
#pragma unroll
    for (int off = 16; off > 0; off >>= 1)
      acc += __shfl_xor_sync(0xffffffffu, acc, off);
    if (lane == 0) g_scores[(size_t)b * SS + q * SQ + sl] = acc;
  }
}

// ---------------------------------------------------------------------------
// Kernel 3: softmax prologue + weighted sum (PDL secondary of scores).
//   out[b, q*256+t] = sum_s softmax(scores[b])[s] * att_feats[b,s,q*256+t]
// Grid: (BB, 4) = 1024 blocks, 256 threads, 1 output dim per thread.
// ---------------------------------------------------------------------------
__global__ __launch_bounds__(256) void wsum_kernel(
    const float* __restrict__ att_feats,
    float* __restrict__ out) {
  __shared__ float sh_w[SS];
  __shared__ float red[8];

  const int b    = blockIdx.x;
  const int q    = blockIdx.y;
  const int tid  = threadIdx.x;
  const int warp = tid >> 5;
  const int lane = tid & 31;

#if defined(__CUDA_ARCH__)
  cudaGridDependencySynchronize();   // scores now visible
#endif

  // --- softmax over 196 scores ---
  const float v = (tid < SS) ? g_scores[(size_t)b * SS + tid] : -INFINITY;

  float m = v;
#pragma unroll
  for (int off = 16; off > 0; off >>= 1)
    m = fmaxf(m, __shfl_xor_sync(0xffffffffu, m, off));
  if (lane == 0) red[warp] = m;
  __syncthreads();
  m = red[0];
#pragma unroll
  for (int i = 1; i < 8; i++) m = fmaxf(m, red[i]);
  __syncthreads();

  const float e = (tid < SS) ? __expf(v - m) : 0.f;
  float sum = e;
#pragma unroll
  for (int off = 16; off > 0; off >>= 1)
    sum += __shfl_xor_sync(0xffffffffu, sum, off);
  if (lane == 0) red[warp] = sum;
  __syncthreads();
  float tot = red[0];
#pragma unroll
  for (int i = 1; i < 8; i++) tot += red[i];
  const float inv = 1.f / tot;
  if (tid < SS) sh_w[tid] = e * inv;
  __syncthreads();

  // --- stream att_feats: 196 coalesced scalar loads per thread ---
  const int d = q * 256 + tid;
  const float* ab = att_feats + (size_t)b * SS * RNN + d;
  float acc = 0.f;
#pragma unroll 4
  for (int s = 0; s < SS; s++)
    acc = fmaf(sh_w[s], ab[(size_t)s * RNN], acc);

  out[(size_t)b * RNN + d] = acc;
}

// ---------------------------------------------------------------------------
// Launch chain: gemm -> reduce -> scores -> wsum, each boundary PDL-overlapped.
// Inputs: h, att_feats, p_att_feats, w_h2att, b_h2att, w_alpha,
// b_alpha (unused: softmax shift-invariant).
// ---------------------------------------------------------------------------
extern "C" void kernel_launch(void* const* d_in, const int* in_sizes, int n_in,
                              void* d_out, int out_size) {
  (void)in_sizes; (void)n_in; (void)out_size;
  const float* h         = (const float*)d_in[0];
  const float* att_feats = (const float*)d_in[1];
  const float* p_att     = (const float*)d_in[2];
  const float* w_h2att   = (const float*)d_in[3];
  const float* b_h2att   = (const float*)d_in[4];
  const float* w_alpha   = (const float*)d_in[5];
  float* out = (float*)d_out;

  dim3 g1(ATTH / 64, BB / 64, KSPLIT);      // (8, 4, 32) = 1024 blocks
  gemm_atth_kernel<<<g1, 256>>>(h, w_h2att);

  cudaLaunchAttribute attr[1];
  attr[0].id = cudaLaunchAttributeProgrammaticStreamSerialization;
  attr[0].val.programmaticStreamSerializationAllowed = 1;

  {
    cudaLaunchConfig_t cfg = {};
    cfg.gridDim  = dim3((BB * ATTH) / 256);   // 512 blocks
    cfg.blockDim = dim3(256);
    cfg.stream   = 0;
    cfg.attrs    = attr;
    cfg.numAttrs = 1;
    cudaLaunchKernelEx(&cfg, reduce_atth_kernel, b_h2att);
  }
  {
    cudaLaunchConfig_t cfg = {};
    cfg.gridDim  = dim3(BB, 4);
    cfg.blockDim = dim3(256);
    cfg.stream   = 0;
    cfg.attrs    = attr;
    cfg.numAttrs = 1;
    cudaLaunchKernelEx(&cfg, scores_kernel, p_att, w_alpha);
  }
  {
    cudaLaunchConfig_t cfg = {};
    cfg.gridDim  = dim3(BB, 4);
    cfg.blockDim = dim3(256);
    cfg.stream   = 0;
    cfg.attrs    = attr;
    cfg.numAttrs = 1;
    cudaLaunchKernelEx(&cfg, wsum_kernel, att_feats, out);
  }
}